// round 1
// baseline (speedup 1.0000x reference)
#include <cuda_runtime.h>
#include <cstdint>

// Problem constants (fixed by the dataset): C=64 in-channels, T=8 terms, F=64 out.
#define C_DIM 64
#define T_DIM 8
#define F_DIM 64
#define TC_DIM 512  // T*C

#define EMAX 800000
#define NOUTMAX 50176  // 50000 rounded up to multiple of 128

// ---------------- scratch (__device__ globals; no allocations allowed) ----------
__device__ int   g_is64;
__device__ int   g_count[NOUTMAX];
__device__ int   g_scan[NOUTMAX];
__device__ int   g_offsets[NOUTMAX + 1];
__device__ int   g_cursor[NOUTMAX];
__device__ int   g_bsum[64];
__device__ int   g_boff[64];
__device__ int   g_src[EMAX];                       // idx_in per CSR slot
__device__ float g_edgeW[(size_t)EMAX * T_DIM];     // 8 edge weights per CSR slot
__device__ float g_M[(size_t)NOUTMAX * TC_DIM];     // (N_OUT, 512) accumulator

// ---------------- index dtype helper --------------------------------------------
__device__ __forceinline__ int idx_at(const void* p, long long i) {
    if (g_is64) return (int)((const long long*)p)[i];
    return ((const int*)p)[i];
}

// Detect int64 vs int32 indices: for int64 (nonneg values < 2^31) every odd
// 32-bit word is zero; for int32 the odd words are idx_in values (≈never all 0).
__global__ void k_detect(const void* idx) {
    if (threadIdx.x == 0 && blockIdx.x == 0) {
        const unsigned* w = (const unsigned*)idx;
        int is64 = 1;
        for (int i = 0; i < 64; i++) {
            if (w[2 * i + 1] != 0u) { is64 = 0; break; }
        }
        g_is64 = is64;
    }
}

// ---------------- CSR build ------------------------------------------------------
__global__ void k_zero(int nOut) {
    int i = blockIdx.x * blockDim.x + threadIdx.x;
    if (i < nOut) g_count[i] = 0;
}

__global__ void k_hist(const void* idx, int E) {
    int e = blockIdx.x * blockDim.x + threadIdx.x;
    if (e < E) {
        int o = idx_at(idx, 2LL * e);
        atomicAdd(&g_count[o], 1);
    }
}

// 3-pass scan: per-block inclusive scans + block-sum scan + fixup.
__global__ void k_scan1(int nOut) {
    __shared__ int sh[1024];
    int tid = threadIdx.x;
    int i = blockIdx.x * 1024 + tid;
    int v = (i < nOut) ? g_count[i] : 0;
    sh[tid] = v;
    __syncthreads();
    for (int off = 1; off < 1024; off <<= 1) {
        int t = (tid >= off) ? sh[tid - off] : 0;
        __syncthreads();
        sh[tid] += t;
        __syncthreads();
    }
    if (i < nOut) g_scan[i] = sh[tid];
    if (tid == 1023) g_bsum[blockIdx.x] = sh[1023];
}

__global__ void k_scan2(int nb) {
    __shared__ int sh[64];
    int tid = threadIdx.x;
    int v = (tid < nb) ? g_bsum[tid] : 0;
    sh[tid] = v;
    __syncthreads();
    for (int off = 1; off < 64; off <<= 1) {
        int t = (tid >= off) ? sh[tid - off] : 0;
        __syncthreads();
        sh[tid] += t;
        __syncthreads();
    }
    g_boff[tid] = sh[tid] - v;  // exclusive
}

__global__ void k_scan3(int nOut, int E) {
    int i = blockIdx.x * 1024 + threadIdx.x;
    if (i < nOut) {
        int off = g_boff[blockIdx.x] + g_scan[i] - g_count[i];
        g_offsets[i] = off;
        g_cursor[i]  = off;
    }
    if (blockIdx.x == 0 && threadIdx.x == 0) g_offsets[nOut] = E;
}

// Fill CSR: also pre-gather per-edge weight vector (transposed to (slot, T)).
__global__ void k_fill(const void* idx, const float* __restrict__ edge, int E) {
    int e = blockIdx.x * blockDim.x + threadIdx.x;
    if (e >= E) return;
    int o  = idx_at(idx, 2LL * e);
    int in = idx_at(idx, 2LL * e + 1);
    int p = atomicAdd(&g_cursor[o], 1);
    g_src[p] = in;
#pragma unroll
    for (int t = 0; t < T_DIM; t++) {
        g_edgeW[(size_t)p * T_DIM + t] = edge[(size_t)t * E + e];
    }
}

// ---------------- edge accumulation: M[o, t*64+c] -------------------------------
// 64 threads per output (one per channel c); each thread keeps s[8] in registers.
__global__ void k_accum(const float* __restrict__ node, int nOut) {
    int tid = threadIdx.x;
    int c = tid & 63;
    int o = blockIdx.x * 4 + (tid >> 6);
    if (o >= nOut) return;

    int beg = g_offsets[o];
    int end = g_offsets[o + 1];

    float s0 = 0.f, s1 = 0.f, s2 = 0.f, s3 = 0.f;
    float s4 = 0.f, s5 = 0.f, s6 = 0.f, s7 = 0.f;

#pragma unroll 2
    for (int i = beg; i < end; i++) {
        int in = g_src[i];
        float4 wa = *reinterpret_cast<const float4*>(g_edgeW + (size_t)i * 8);
        float4 wb = *reinterpret_cast<const float4*>(g_edgeW + (size_t)i * 8 + 4);
        float nv = node[(size_t)in * C_DIM + c];
        s0 += wa.x * nv; s1 += wa.y * nv; s2 += wa.z * nv; s3 += wa.w * nv;
        s4 += wb.x * nv; s5 += wb.y * nv; s6 += wb.z * nv; s7 += wb.w * nv;
    }

    size_t base = (size_t)o * TC_DIM + c;
    g_M[base + 0 * 64] = s0; g_M[base + 1 * 64] = s1;
    g_M[base + 2 * 64] = s2; g_M[base + 3 * 64] = s3;
    g_M[base + 4 * 64] = s4; g_M[base + 5 * 64] = s5;
    g_M[base + 6 * 64] = s6; g_M[base + 7 * 64] = s7;
}

// ---------------- GEMM: out = M(N_OUT x 512) @ Kflat(512 x 64) + bias -----------
#define BM 128
#define BN 64
#define BK 16
#define TM 8
#define TN 4

__global__ __launch_bounds__(256) void k_gemm(const float* __restrict__ Kf,
                                              const float* __restrict__ bias,
                                              float* __restrict__ out, int nOut) {
    __shared__ float Ms[BK][BM + 4];
    __shared__ float Ns[BK][BN + 4];

    int tid = threadIdx.x;
    int tx = tid & 15;   // 16 column groups of 4
    int ty = tid >> 4;   // 16 row groups of 8
    int row0 = blockIdx.x * BM;

    float acc[TM][TN];
#pragma unroll
    for (int i = 0; i < TM; i++)
#pragma unroll
        for (int j = 0; j < TN; j++) acc[i][j] = 0.f;

    for (int kb = 0; kb < TC_DIM; kb += BK) {
        // Load M tile: 128x16 = 512 float4, 2 per thread.
#pragma unroll
        for (int r = 0; r < 2; r++) {
            int idx = tid + r * 256;        // 0..511
            int m  = idx >> 2;              // 0..127
            int k4 = idx & 3;               // 0..3
            int row = row0 + m;
            float4 v = make_float4(0.f, 0.f, 0.f, 0.f);
            if (row < nOut)
                v = *reinterpret_cast<const float4*>(&g_M[(size_t)row * TC_DIM + kb + k4 * 4]);
            Ms[k4 * 4 + 0][m] = v.x;
            Ms[k4 * 4 + 1][m] = v.y;
            Ms[k4 * 4 + 2][m] = v.z;
            Ms[k4 * 4 + 3][m] = v.w;
        }
        // Load K tile: 16x64 = 256 float4, 1 per thread.
        {
            int k  = tid >> 4;   // 0..15
            int f4 = tid & 15;   // 0..15
            float4 v = *reinterpret_cast<const float4*>(&Kf[(size_t)(kb + k) * F_DIM + f4 * 4]);
            Ns[k][f4 * 4 + 0] = v.x;
            Ns[k][f4 * 4 + 1] = v.y;
            Ns[k][f4 * 4 + 2] = v.z;
            Ns[k][f4 * 4 + 3] = v.w;
        }
        __syncthreads();

#pragma unroll
        for (int k = 0; k < BK; k++) {
            float a[TM];
            float4 a0 = *reinterpret_cast<const float4*>(&Ms[k][ty * TM]);
            float4 a1 = *reinterpret_cast<const float4*>(&Ms[k][ty * TM + 4]);
            a[0] = a0.x; a[1] = a0.y; a[2] = a0.z; a[3] = a0.w;
            a[4] = a1.x; a[5] = a1.y; a[6] = a1.z; a[7] = a1.w;
            float4 b4 = *reinterpret_cast<const float4*>(&Ns[k][tx * TN]);
            float b[TN] = {b4.x, b4.y, b4.z, b4.w};
#pragma unroll
            for (int i = 0; i < TM; i++)
#pragma unroll
                for (int j = 0; j < TN; j++) acc[i][j] += a[i] * b[j];
        }
        __syncthreads();
    }

    float4 bv = *reinterpret_cast<const float4*>(&bias[tx * TN]);
#pragma unroll
    for (int i = 0; i < TM; i++) {
        int row = row0 + ty * TM + i;
        if (row < nOut) {
            float4 o4 = make_float4(acc[i][0] + bv.x, acc[i][1] + bv.y,
                                    acc[i][2] + bv.z, acc[i][3] + bv.w);
            *reinterpret_cast<float4*>(&out[(size_t)row * F_DIM + tx * TN]) = o4;
        }
    }
}

// ---------------- launch ---------------------------------------------------------
extern "C" void kernel_launch(void* const* d_in, const int* in_sizes, int n_in,
                              void* d_out, int out_size) {
    const float* node = (const float*)d_in[0];
    const float* edge = (const float*)d_in[1];
    const void*  idx  = d_in[2];
    const float* kern = (const float*)d_in[3];
    const float* bias = (const float*)d_in[4];
    float* out = (float*)d_out;

    int E    = in_sizes[1] / T_DIM;   // edge_features is (T, E)
    int nOut = out_size / F_DIM;      // output is (N_OUT, F)
    int nb   = (nOut + 1023) / 1024;

    k_detect<<<1, 32>>>(idx);
    k_zero<<<(nOut + 255) / 256, 256>>>(nOut);
    k_hist<<<(E + 255) / 256, 256>>>(idx, E);
    k_scan1<<<nb, 1024>>>(nOut);
    k_scan2<<<1, 64>>>(nb);
    k_scan3<<<nb, 1024>>>(nOut, E);
    k_fill<<<(E + 255) / 256, 256>>>(idx, edge, E);
    k_accum<<<(nOut + 3) / 4, 256>>>(node, nOut);
    k_gemm<<<(nOut + BM - 1) / BM, 256>>>(kern, bias, out, nOut);
}